// round 5
// baseline (speedup 1.0000x reference)
#include <cuda_runtime.h>
#include <cstdint>

#define T_STEPS 2048
#define BATCH   64
#define IN_DIM  128
#define HDIM    256
#define OUT_DIM 128
#define KTOT    384
#define NTHR    256
#define CLUSTER 8
#define NBLK    128           // 16 batch-groups x 8 col-blocks
#define WPAD    388           // weight row pad: conflict-free LDS.128
#define WOPAD   260

// smem layout (floats)
#define OFF_ACT   0                       // [2][384][4]      = 3072
#define OFF_W     3072                    // [4][32][388]     = 49664
#define OFF_WOUT  52736                   // [16][260]        = 4160
#define OFF_P     56896                   // [4][32][4]       = 512
#define OFF_BIAS  57408                   // 128
#define OFF_BOUT  57536                   // 16
#define SMEM_FLOATS 57552
#define SMEM_BYTES (SMEM_FLOATS * 4)      // 230208 <= 232448 (227KB)

__device__ __forceinline__ void cluster_sync_all() {
    asm volatile("barrier.cluster.arrive.aligned;" ::: "memory");
    asm volatile("barrier.cluster.wait.aligned;" ::: "memory");
}

__global__ void __launch_bounds__(NTHR, 1) __cluster_dims__(CLUSTER, 1, 1)
lstm_cluster_kernel(
    const float* __restrict__ input,   // [T, B, IN]
    const float* __restrict__ W_ih,    // [4H, IN]
    const float* __restrict__ W_hh,    // [4H, H]
    const float* __restrict__ b_ih,    // [4H]
    const float* __restrict__ b_hh,    // [4H]
    const float* __restrict__ W_out,   // [OUT, H]
    const float* __restrict__ b_out,   // [OUT]
    float* __restrict__ out,
    int out_size)
{
    extern __shared__ float sm[];
    float* sAct  = sm + OFF_ACT;   // [buf][k][row]: k<128 = x, k>=128 = h
    float* sW    = sm + OFF_W;     // [(g*32+m)][k pad 388]
    float* sWo   = sm + OFF_WOUT;  // [ocl][k pad 260]
    float* sP    = sm + OFF_P;     // [(g*32+m)][row]
    float* sBias = sm + OFF_BIAS;
    float* sBOut = sm + OFF_BOUT;

    const int tid  = threadIdx.x;
    const int wgrp = tid >> 5;
    const int lane = tid & 31;
    uint32_t rank;
    asm("mov.u32 %0, %%cluster_ctarank;" : "=r"(rank));
    const int grp   = blockIdx.x >> 3;     // batch group
    const int rbase = grp * 4;             // batch rows rbase..rbase+3
    const int cb    = (int)rank * 32;      // h column base

    // ---- preload weights ----
    for (int i = tid; i < 4 * 32 * KTOT; i += NTHR) {
        int g = i / (32 * KTOT);
        int rem = i % (32 * KTOT);
        int m = rem / KTOT, k = rem % KTOT;
        int grow = g * HDIM + cb + m;
        float w = (k < IN_DIM) ? W_ih[grow * IN_DIM + k]
                               : W_hh[grow * HDIM + (k - IN_DIM)];
        sW[(g * 32 + m) * WPAD + k] = w;
    }
    for (int i = tid; i < 16 * HDIM; i += NTHR) {
        int o = i >> 8, k = i & 255;
        sWo[o * WOPAD + k] = W_out[((int)rank * 16 + o) * HDIM + k];
    }
    if (tid < 128) {
        int g = tid >> 5, m = tid & 31;
        int grow = g * HDIM + cb + m;
        sBias[tid] = b_ih[grow] + b_hh[grow];
    }
    if (tid < 16) sBOut[tid] = b_out[(int)rank * 16 + tid];

    // ---- init act buf0 (h must be 0) ----
    for (int i = tid; i < KTOT * 4; i += NTHR) sAct[i] = 0.0f;
    __syncthreads();
    if (tid < 128) {   // x_0 transposed into buf0
        int r = tid >> 5, kq = tid & 31;
        float4 v = *(const float4*)(input + ((size_t)0 * BATCH + rbase + r) * IN_DIM + kq * 4);
        sAct[(kq * 4 + 0) * 4 + r] = v.x;
        sAct[(kq * 4 + 1) * 4 + r] = v.y;
        sAct[(kq * 4 + 2) * 4 + r] = v.z;
        sAct[(kq * 4 + 3) * 4 + r] = v.w;
    }
    __syncthreads();

    // mapa'd act bases for all 8 cluster CTAs
    uint32_t actB = (uint32_t)__cvta_generic_to_shared(sAct);
    uint32_t peerB[CLUSTER];
    #pragma unroll
    for (int p = 0; p < CLUSTER; p++)
        asm("mapa.shared::cluster.u32 %0, %1, %2;" : "=r"(peerB[p]) : "r"(actB), "r"(p));

    cluster_sync_all();

    const size_t Y_TOTAL = (size_t)T_STEPS * BATCH * OUT_DIM;
    const bool write_tail = (out_size >= (int)(Y_TOTAL + 2 * BATCH * HDIM));

    float c_reg = 0.0f;   // cell state for (row=wgrp, col=cb+lane), warps 0-3

    for (int t = 0; t < T_STEPS; t++) {
        const int buf = t & 1;
        const float* A = sAct + buf * (KTOT * 4);

        if (tid < 128) {
            // ---- gate GEMM: warp g computes gate g, col m=lane, rows 0-3 ----
            const int g = wgrp, m = lane;
            const float bias = sBias[g * 32 + m];
            float a0 = bias, a1 = bias, a2 = bias, a3 = bias;
            const float4* wv = (const float4*)(sW + (g * 32 + m) * WPAD);
            const float4* av = (const float4*)A;
            #pragma unroll 4
            for (int kk = 0; kk < KTOT / 4; kk++) {
                float4 w = wv[kk];
                float4 p;
                p = av[kk * 4 + 0];
                a0 += w.x * p.x; a1 += w.x * p.y; a2 += w.x * p.z; a3 += w.x * p.w;
                p = av[kk * 4 + 1];
                a0 += w.y * p.x; a1 += w.y * p.y; a2 += w.y * p.z; a3 += w.y * p.w;
                p = av[kk * 4 + 2];
                a0 += w.z * p.x; a1 += w.z * p.y; a2 += w.z * p.z; a3 += w.z * p.w;
                p = av[kk * 4 + 3];
                a0 += w.w * p.x; a1 += w.w * p.y; a2 += w.w * p.z; a3 += w.w * p.w;
            }
            *(float4*)(sP + (g * 32 + m) * 4) = make_float4(a0, a1, a2, a3);
            asm volatile("bar.sync 1, 128;" ::: "memory");

            // ---- cell: thread (row=wgrp, col m=lane) ----
            const int r = wgrp;
            float gi = sP[(0 * 32 + m) * 4 + r];
            float gf = sP[(1 * 32 + m) * 4 + r];
            float gg = sP[(2 * 32 + m) * 4 + r];
            float go = sP[(3 * 32 + m) * 4 + r];
            float i_ = 1.0f / (1.0f + __expf(-gi));
            float f_ = 1.0f / (1.0f + __expf(-gf));
            float g_ = tanhf(gg);
            float o_ = 1.0f / (1.0f + __expf(-go));
            float cn = f_ * c_reg + i_ * g_;
            float hn = o_ * tanhf(cn);
            c_reg = cn;

            // push h_new to all 8 cluster CTAs (buf^1, transposed layout)
            uint32_t off = (uint32_t)(((1 - buf) * (KTOT * 4)
                                       + (IN_DIM + cb + m) * 4 + r) * 4);
            #pragma unroll
            for (int p = 0; p < CLUSTER; p++)
                asm volatile("st.shared::cluster.f32 [%0], %1;"
                             :: "r"(peerB[p] + off), "f"(hn) : "memory");

            if (t == T_STEPS - 1 && write_tail) {
                out[Y_TOTAL + (size_t)(rbase + r) * HDIM + cb + m] = hn;
                out[Y_TOTAL + BATCH * HDIM + (size_t)(rbase + r) * HDIM + cb + m] = cn;
            }
        } else {
            // ---- warps 4-7: x_{t+1} prefetch (transposed) ----
            const int tid2 = tid - 128;
            const int xr = tid2 >> 5, xkq = tid2 & 31;
            if (t + 1 < T_STEPS) {
                float4 v = __ldg((const float4*)(input
                            + ((size_t)(t + 1) * BATCH + rbase + xr) * IN_DIM + xkq * 4));
                float* dst = sAct + (1 - buf) * (KTOT * 4);
                dst[(xkq * 4 + 0) * 4 + xr] = v.x;
                dst[(xkq * 4 + 1) * 4 + xr] = v.y;
                dst[(xkq * 4 + 2) * 4 + xr] = v.z;
                dst[(xkq * 4 + 3) * 4 + xr] = v.w;
            }
            // ---- y_{t-1} = h_t @ W_out^T (16 out-cols for this CTA) ----
            if (t > 0) {
                const int w4  = wgrp - 4;
                const int ocl = w4 * 4 + (lane & 3);
                const int k0  = (lane >> 2) * 32;
                float y0 = 0.f, y1 = 0.f, y2 = 0.f, y3 = 0.f;
                const float4* wv = (const float4*)(sWo + ocl * WOPAD + k0);
                const float4* av = (const float4*)(A + (IN_DIM + k0) * 4);
                #pragma unroll
                for (int kk = 0; kk < 8; kk++) {
                    float4 w = wv[kk];
                    float4 p;
                    p = av[kk * 4 + 0];
                    y0 += w.x * p.x; y1 += w.x * p.y; y2 += w.x * p.z; y3 += w.x * p.w;
                    p = av[kk * 4 + 1];
                    y0 += w.y * p.x; y1 += w.y * p.y; y2 += w.y * p.z; y3 += w.y * p.w;
                    p = av[kk * 4 + 2];
                    y0 += w.z * p.x; y1 += w.z * p.y; y2 += w.z * p.z; y3 += w.z * p.w;
                    p = av[kk * 4 + 3];
                    y0 += w.w * p.x; y1 += w.w * p.y; y2 += w.w * p.z; y3 += w.w * p.w;
                }
                #pragma unroll
                for (int s = 4; s <= 16; s <<= 1) {
                    y0 += __shfl_xor_sync(0xffffffffu, y0, s);
                    y1 += __shfl_xor_sync(0xffffffffu, y1, s);
                    y2 += __shfl_xor_sync(0xffffffffu, y2, s);
                    y3 += __shfl_xor_sync(0xffffffffu, y3, s);
                }
                if ((lane >> 2) == 0) {
                    float b = sBOut[ocl];
                    size_t yb = ((size_t)(t - 1) * BATCH + rbase) * OUT_DIM
                                + (size_t)rank * 16 + ocl;
                    out[yb + 0 * OUT_DIM] = y0 + b;
                    out[yb + 1 * OUT_DIM] = y1 + b;
                    out[yb + 2 * OUT_DIM] = y2 + b;
                    out[yb + 3 * OUT_DIM] = y3 + b;
                }
            }
        }
        cluster_sync_all();
    }

    // ---- tail: y_{T-1} from h_T (in buf 0 after final sync) ----
    if (tid >= 128) {
        const float* A = sAct + (T_STEPS & 1) * (KTOT * 4);
        const int w4  = wgrp - 4;
        const int ocl = w4 * 4 + (lane & 3);
        const int k0  = (lane >> 2) * 32;
        float y0 = 0.f, y1 = 0.f, y2 = 0.f, y3 = 0.f;
        const float4* wv = (const float4*)(sWo + ocl * WOPAD + k0);
        const float4* av = (const float4*)(A + (IN_DIM + k0) * 4);
        #pragma unroll
        for (int kk = 0; kk < 8; kk++) {
            float4 w = wv[kk];
            float4 p;
            p = av[kk * 4 + 0];
            y0 += w.x * p.x; y1 += w.x * p.y; y2 += w.x * p.z; y3 += w.x * p.w;
            p = av[kk * 4 + 1];
            y0 += w.y * p.x; y1 += w.y * p.y; y2 += w.y * p.z; y3 += w.y * p.w;
            p = av[kk * 4 + 2];
            y0 += w.z * p.x; y1 += w.z * p.y; y2 += w.z * p.z; y3 += w.z * p.w;
            p = av[kk * 4 + 3];
            y0 += w.w * p.x; y1 += w.w * p.y; y2 += w.w * p.z; y3 += w.w * p.w;
        }
        #pragma unroll
        for (int s = 4; s <= 16; s <<= 1) {
            y0 += __shfl_xor_sync(0xffffffffu, y0, s);
            y1 += __shfl_xor_sync(0xffffffffu, y1, s);
            y2 += __shfl_xor_sync(0xffffffffu, y2, s);
            y3 += __shfl_xor_sync(0xffffffffu, y3, s);
        }
        if ((lane >> 2) == 0) {
            float b = sBOut[ocl];
            size_t yb = ((size_t)(T_STEPS - 1) * BATCH + rbase) * OUT_DIM
                        + (size_t)rank * 16 + ocl;
            out[yb + 0 * OUT_DIM] = y0 + b;
            out[yb + 1 * OUT_DIM] = y1 + b;
            out[yb + 2 * OUT_DIM] = y2 + b;
            out[yb + 3 * OUT_DIM] = y3 + b;
        }
    }
    cluster_sync_all();   // no CTA exits while peers may still DSMEM-access it
}

extern "C" void kernel_launch(void* const* d_in, const int* in_sizes, int n_in,
                              void* d_out, int out_size) {
    const float* input = (const float*)d_in[0];
    const float* W_ih  = (const float*)d_in[1];
    const float* W_hh  = (const float*)d_in[2];
    const float* b_ih  = (const float*)d_in[3];
    const float* b_hh  = (const float*)d_in[4];
    const float* W_out = (const float*)d_in[5];
    const float* b_out = (const float*)d_in[6];
    float* out = (float*)d_out;
    (void)in_sizes; (void)n_in;

    cudaFuncSetAttribute(lstm_cluster_kernel,
                         cudaFuncAttributeMaxDynamicSharedMemorySize, SMEM_BYTES);
    lstm_cluster_kernel<<<NBLK, NTHR, SMEM_BYTES>>>(
        input, W_ih, W_hh, b_ih, b_hh, W_out, b_out, out, out_size);
}

// round 6
// speedup vs baseline: 2.1004x; 2.1004x over previous
#include <cuda_runtime.h>
#include <cstdint>

#define T_STEPS 2048
#define BATCH   64
#define IN_DIM  128
#define HDIM    256
#define OUT_DIM 128
#define KTOT    384
#define NTHR    256
#define NBLK    128           // 16 batch-groups x 8 col-blocks
#define WPAD    388
#define WOPAD   260

// smem layout (floats)
#define OFF_ACT   0                       // [2][384][4]  = 3072
#define OFF_W     3072                    // [4*32][388]  = 49664
#define OFF_WOUT  52736                   // [16][260]    = 4160
#define OFF_P     56896                   // [4*32][4]    = 512
#define OFF_BIAS  57408                   // 128
#define OFF_BOUT  57536                   // 16
#define SMEM_FLOATS 57552
#define SMEM_BYTES (SMEM_FLOATS * 4)      // 230208

// persistent state: transposed h, double-buffered per group
__device__ float g_hT[16][2][HDIM * 4];   // [grp][buf][k*4 + r]
struct Flag { unsigned v; unsigned pad[31]; };
__device__ Flag g_flags[NBLK];

__device__ __forceinline__ unsigned ld_acq(const unsigned* p) {
    unsigned v;
    asm volatile("ld.acquire.gpu.global.u32 %0, [%1];" : "=r"(v) : "l"(p) : "memory");
    return v;
}
__device__ __forceinline__ void st_rel(unsigned* p, unsigned v) {
    asm volatile("st.release.gpu.global.u32 [%0], %1;" :: "l"(p), "r"(v) : "memory");
}

__global__ void __launch_bounds__(NTHR, 1) lstm_grouped_kernel(
    const float* __restrict__ input,   // [T, B, IN]
    const float* __restrict__ W_ih,    // [4H, IN]
    const float* __restrict__ W_hh,    // [4H, H]
    const float* __restrict__ b_ih,    // [4H]
    const float* __restrict__ b_hh,    // [4H]
    const float* __restrict__ W_out,   // [OUT, H]
    const float* __restrict__ b_out,   // [OUT]
    float* __restrict__ out,
    int out_size)
{
    extern __shared__ float sm[];
    float* sAct  = sm + OFF_ACT;   // [buf][k][r]: k<128 = x, k>=128 = h
    float* sW    = sm + OFF_W;
    float* sWo   = sm + OFF_WOUT;
    float* sP    = sm + OFF_P;
    float* sBias = sm + OFF_BIAS;
    float* sBOut = sm + OFF_BOUT;

    const int tid  = threadIdx.x;
    const int wgrp = tid >> 5;
    const int lane = tid & 31;
    const int bid  = blockIdx.x;
    const int grp  = bid >> 3;          // batch group (4 rows)
    const int rank = bid & 7;           // column block (32 h-cols)
    const int rbase = grp * 4;
    const int cb    = rank * 32;

    const unsigned base = ld_acq(&g_flags[bid].v);   // uniform within group

    // ---- preload weights ----
    for (int i = tid; i < 4 * 32 * KTOT; i += NTHR) {
        int g = i / (32 * KTOT);
        int rem = i % (32 * KTOT);
        int m = rem / KTOT, k = rem % KTOT;
        int grow = g * HDIM + cb + m;
        float w = (k < IN_DIM) ? W_ih[grow * IN_DIM + k]
                               : W_hh[grow * HDIM + (k - IN_DIM)];
        sW[(g * 32 + m) * WPAD + k] = w;
    }
    for (int i = tid; i < 16 * HDIM; i += NTHR) {
        int o = i >> 8, k = i & 255;
        sWo[o * WOPAD + k] = W_out[(rank * 16 + o) * HDIM + k];
    }
    if (tid < 128) {
        int g = tid >> 5, m = tid & 31;
        int grow = g * HDIM + cb + m;
        sBias[tid] = b_ih[grow] + b_hh[grow];
    }
    if (tid < 16) sBOut[tid] = b_out[rank * 16 + tid];

    // zero act buf0; x_0 transposed into buf0
    for (int i = tid; i < KTOT * 4; i += NTHR) sAct[i] = 0.0f;
    __syncthreads();
    if (tid < 128) {
        int r = tid >> 5, kq = tid & 31;
        float4 v = *(const float4*)(input + ((size_t)rbase + r) * IN_DIM + kq * 4);
        sAct[(kq * 4 + 0) * 4 + r] = v.x;
        sAct[(kq * 4 + 1) * 4 + r] = v.y;
        sAct[(kq * 4 + 2) * 4 + r] = v.z;
        sAct[(kq * 4 + 3) * 4 + r] = v.w;
    }
    // zero our slice of g_hT[grp][0] (h_0 = 0)
    if (tid < 128) {
        int m = tid & 31, r = tid >> 5;
        g_hT[grp][0][(cb + m) * 4 + r] = 0.0f;
    }
    __syncthreads();

    // ---- init group barrier ----
    if (tid == 0) st_rel(&g_flags[bid].v, base + 1);
    if (tid < 8) {
        const unsigned* p = &g_flags[grp * 8 + tid].v;
        while (ld_acq(p) < base + 1) { }
    }
    __syncthreads();

    const size_t Y_TOTAL = (size_t)T_STEPS * BATCH * OUT_DIM;
    const bool write_tail = (out_size >= (int)(Y_TOTAL + 2 * BATCH * HDIM));

    float c_reg = 0.0f;   // cell state for (row=wgrp, col=cb+lane), warps 0-3

    for (int t = 0; t < T_STEPS; t++) {
        const int buf = t & 1;
        float* A = sAct + buf * (KTOT * 4);

        // ---- fill h region of A from g_hT[grp][buf] (linear, L1-bypass) ----
        {
            float4 v = __ldcg(((const float4*)g_hT[grp][buf]) + tid);
            ((float4*)A)[128 + tid] = v;
        }
        __syncthreads();

        const unsigned tgt = base + 2 + (unsigned)t;

        if (tid < 128) {
            // ---- gate GEMM: warp g = gate g, col m=lane, rows 0-3, K=384 ----
            const int g = wgrp, m = lane;
            const float bias = sBias[g * 32 + m];
            float a0 = bias, a1 = bias, a2 = bias, a3 = bias;
            const float4* wv = (const float4*)(sW + (g * 32 + m) * WPAD);
            const float4* av = (const float4*)A;
            #pragma unroll 4
            for (int kk = 0; kk < KTOT / 4; kk++) {
                float4 w = wv[kk];
                float4 p;
                p = av[kk * 4 + 0];
                a0 += w.x * p.x; a1 += w.x * p.y; a2 += w.x * p.z; a3 += w.x * p.w;
                p = av[kk * 4 + 1];
                a0 += w.y * p.x; a1 += w.y * p.y; a2 += w.y * p.z; a3 += w.y * p.w;
                p = av[kk * 4 + 2];
                a0 += w.z * p.x; a1 += w.z * p.y; a2 += w.z * p.z; a3 += w.z * p.w;
                p = av[kk * 4 + 3];
                a0 += w.w * p.x; a1 += w.w * p.y; a2 += w.w * p.z; a3 += w.w * p.w;
            }
            *(float4*)(sP + (g * 32 + m) * 4) = make_float4(a0, a1, a2, a3);
            asm volatile("bar.sync 1, 128;" ::: "memory");

            // ---- cell: thread (row r=wgrp, col m=lane) ----
            const int r = wgrp;
            float gi = sP[(0 * 32 + m) * 4 + r];
            float gf = sP[(1 * 32 + m) * 4 + r];
            float gg = sP[(2 * 32 + m) * 4 + r];
            float go = sP[(3 * 32 + m) * 4 + r];
            float i_ = 1.0f / (1.0f + __expf(-gi));
            float f_ = 1.0f / (1.0f + __expf(-gf));
            float g_ = tanhf(gg);
            float o_ = 1.0f / (1.0f + __expf(-go));
            float cn = f_ * c_reg + i_ * g_;
            float hn = o_ * tanhf(cn);
            c_reg = cn;

            __stcg(&g_hT[grp][1 - buf][(cb + m) * 4 + r], hn);

            if (t == T_STEPS - 1 && write_tail) {
                out[Y_TOTAL + (size_t)(rbase + r) * HDIM + cb + m] = hn;
                out[Y_TOTAL + BATCH * HDIM + (size_t)(rbase + r) * HDIM + cb + m] = cn;
            }
            asm volatile("bar.sync 1, 128;" ::: "memory");
            if (tid == 0) st_rel(&g_flags[bid].v, tgt);
        } else {
            // ---- warps 4-7: x_{t+1} prefetch (transposed) ----
            const int tid2 = tid - 128;
            const int xr = tid2 >> 5, xkq = tid2 & 31;
            if (t + 1 < T_STEPS) {
                float4 v = __ldcg((const float4*)(input
                            + ((size_t)(t + 1) * BATCH + rbase + xr) * IN_DIM + xkq * 4));
                float* dst = sAct + (1 - buf) * (KTOT * 4);
                dst[(xkq * 4 + 0) * 4 + xr] = v.x;
                dst[(xkq * 4 + 1) * 4 + xr] = v.y;
                dst[(xkq * 4 + 2) * 4 + xr] = v.z;
                dst[(xkq * 4 + 3) * 4 + xr] = v.w;
            }
            // ---- y_{t-1} = h_t @ W_out^T (16 out-cols for this rank) ----
            if (t > 0) {
                const int w4  = wgrp - 4;
                const int ocl = w4 * 4 + (lane & 3);
                const int k0  = (lane >> 2) * 32;
                float y0 = 0.f, y1 = 0.f, y2 = 0.f, y3 = 0.f;
                const float4* wv = (const float4*)(sWo + ocl * WOPAD + k0);
                const float4* av = (const float4*)(A + (IN_DIM + k0) * 4);
                #pragma unroll
                for (int kk = 0; kk < 8; kk++) {
                    float4 w = wv[kk];
                    float4 p;
                    p = av[kk * 4 + 0];
                    y0 += w.x * p.x; y1 += w.x * p.y; y2 += w.x * p.z; y3 += w.x * p.w;
                    p = av[kk * 4 + 1];
                    y0 += w.y * p.x; y1 += w.y * p.y; y2 += w.y * p.z; y3 += w.y * p.w;
                    p = av[kk * 4 + 2];
                    y0 += w.z * p.x; y1 += w.z * p.y; y2 += w.z * p.z; y3 += w.z * p.w;
                    p = av[kk * 4 + 3];
                    y0 += w.w * p.x; y1 += w.w * p.y; y2 += w.w * p.z; y3 += w.w * p.w;
                }
                #pragma unroll
                for (int s = 4; s <= 16; s <<= 1) {
                    y0 += __shfl_xor_sync(0xffffffffu, y0, s);
                    y1 += __shfl_xor_sync(0xffffffffu, y1, s);
                    y2 += __shfl_xor_sync(0xffffffffu, y2, s);
                    y3 += __shfl_xor_sync(0xffffffffu, y3, s);
                }
                if ((lane >> 2) == 0) {
                    float b = sBOut[ocl];
                    size_t yb = ((size_t)(t - 1) * BATCH + rbase) * OUT_DIM
                                + (size_t)rank * 16 + ocl;
                    out[yb + 0 * OUT_DIM] = y0 + b;
                    out[yb + 1 * OUT_DIM] = y1 + b;
                    out[yb + 2 * OUT_DIM] = y2 + b;
                    out[yb + 3 * OUT_DIM] = y3 + b;
                }
            }
        }

        // ---- group poll: 8 flags, threads 0-7 ----
        if (tid < 8) {
            const unsigned* p = &g_flags[grp * 8 + tid].v;
            while (ld_acq(p) < tgt) { }
        }
        __syncthreads();
    }

    // ---- tail: y_{T-1} from h_T (g_hT[grp][0]) ----
    {
        float4 v = __ldcg(((const float4*)g_hT[grp][T_STEPS & 1]) + tid);
        ((float4*)(sAct + (T_STEPS & 1) * (KTOT * 4)))[128 + tid] = v;
    }
    __syncthreads();
    if (tid >= 128) {
        const float* A = sAct + (T_STEPS & 1) * (KTOT * 4);
        const int w4  = wgrp - 4;
        const int ocl = w4 * 4 + (lane & 3);
        const int k0  = (lane >> 2) * 32;
        float y0 = 0.f, y1 = 0.f, y2 = 0.f, y3 = 0.f;
        const float4* wv = (const float4*)(sWo + ocl * WOPAD + k0);
        const float4* av = (const float4*)(A + (IN_DIM + k0) * 4);
        #pragma unroll
        for (int kk = 0; kk < 8; kk++) {
            float4 w = wv[kk];
            float4 p;
            p = av[kk * 4 + 0];
            y0 += w.x * p.x; y1 += w.x * p.y; y2 += w.x * p.z; y3 += w.x * p.w;
            p = av[kk * 4 + 1];
            y0 += w.y * p.x; y1 += w.y * p.y; y2 += w.y * p.z; y3 += w.y * p.w;
            p = av[kk * 4 + 2];
            y0 += w.z * p.x; y1 += w.z * p.y; y2 += w.z * p.z; y3 += w.z * p.w;
            p = av[kk * 4 + 3];
            y0 += w.w * p.x; y1 += w.w * p.y; y2 += w.w * p.z; y3 += w.w * p.w;
        }
        #pragma unroll
        for (int s = 4; s <= 16; s <<= 1) {
            y0 += __shfl_xor_sync(0xffffffffu, y0, s);
            y1 += __shfl_xor_sync(0xffffffffu, y1, s);
            y2 += __shfl_xor_sync(0xffffffffu, y2, s);
            y3 += __shfl_xor_sync(0xffffffffu, y3, s);
        }
        if ((lane >> 2) == 0) {
            float b = sBOut[ocl];
            size_t yb = ((size_t)(T_STEPS - 1) * BATCH + rbase) * OUT_DIM
                        + (size_t)rank * 16 + ocl;
            out[yb + 0 * OUT_DIM] = y0 + b;
            out[yb + 1 * OUT_DIM] = y1 + b;
            out[yb + 2 * OUT_DIM] = y2 + b;
            out[yb + 3 * OUT_DIM] = y3 + b;
        }
    }
}

extern "C" void kernel_launch(void* const* d_in, const int* in_sizes, int n_in,
                              void* d_out, int out_size) {
    const float* input = (const float*)d_in[0];
    const float* W_ih  = (const float*)d_in[1];
    const float* W_hh  = (const float*)d_in[2];
    const float* b_ih  = (const float*)d_in[3];
    const float* b_hh  = (const float*)d_in[4];
    const float* W_out = (const float*)d_in[5];
    const float* b_out = (const float*)d_in[6];
    float* out = (float*)d_out;
    (void)in_sizes; (void)n_in;

    cudaFuncSetAttribute(lstm_grouped_kernel,
                         cudaFuncAttributeMaxDynamicSharedMemorySize, SMEM_BYTES);
    lstm_grouped_kernel<<<NBLK, NTHR, SMEM_BYTES>>>(
        input, W_ih, W_hh, b_ih, b_hh, W_out, b_out, out, out_size);
}

// round 7
// speedup vs baseline: 4.8308x; 2.2999x over previous
#include <cuda_runtime.h>
#include <cstdint>

#define T_STEPS 2048
#define BATCH   64
#define IN_DIM  128
#define HDIM    256
#define OUT_DIM 128
#define KTOT    384
#define NTHR    512
#define NBLK    128           // 16 batch-groups x 8 col-blocks
#define WOPAD   272           // 272 % 32 == 16 -> conflict-free y-GEMM scalar loads

// smem layout (floats)
#define OFF_ACT   0                       // [2][384][4]  = 3072
#define OFF_WOUT  3072                    // [16][272]    = 4352
#define OFF_P     7424                    // [4][128][4]  = 2048
#define OFF_G     9472                    // [128][4]     = 512
#define OFF_BIAS  9984                    // 128
#define OFF_BOUT  10112                   // 16
#define SMEM_FLOATS 10128
#define SMEM_BYTES (SMEM_FLOATS * 4)      // 40512

// persistent state: transposed h, double-buffered per group
__device__ float g_hT[16][2][HDIM * 4];   // [grp][buf][col*4 + r]
struct Flag { unsigned v; unsigned pad[31]; };
__device__ Flag g_flags[NBLK];

__device__ __forceinline__ unsigned ld_acq(const unsigned* p) {
    unsigned v;
    asm volatile("ld.acquire.gpu.global.u32 %0, [%1];" : "=r"(v) : "l"(p) : "memory");
    return v;
}
__device__ __forceinline__ void st_rel(unsigned* p, unsigned v) {
    asm volatile("st.release.gpu.global.u32 [%0], %1;" :: "l"(p), "r"(v) : "memory");
}

__global__ void __launch_bounds__(NTHR, 1) lstm_fat_kernel(
    const float* __restrict__ input,   // [T, B, IN]
    const float* __restrict__ W_ih,    // [4H, IN]
    const float* __restrict__ W_hh,    // [4H, H]
    const float* __restrict__ b_ih,    // [4H]
    const float* __restrict__ b_hh,    // [4H]
    const float* __restrict__ W_out,   // [OUT, H]
    const float* __restrict__ b_out,   // [OUT]
    float* __restrict__ out,
    int out_size)
{
    extern __shared__ float sm[];
    float* sAct  = sm + OFF_ACT;   // [buf][k][r]: k<128 = x, k>=128 = h
    float* sWo   = sm + OFF_WOUT;
    float* sP    = sm + OFF_P;     // split-K partials
    float* sG    = sm + OFF_G;     // reduced gates [m][r]
    float* sBias = sm + OFF_BIAS;
    float* sBOut = sm + OFF_BOUT;

    const int tid  = threadIdx.x;
    const int bid  = blockIdx.x;
    const int grp  = bid >> 3;          // batch group (4 rows)
    const int rank = bid & 7;           // column block (32 h-cols)
    const int rbase = grp * 4;
    const int cb    = rank * 32;

    const unsigned base = ld_acq(&g_flags[bid].v);

    // ---- gate-GEMM mapping: thread = (gate-col m, k-quarter kq) ----
    const int m   = tid & 127;          // 0..127: g = m>>5 (i,f,g,o), col = m&31
    const int kq  = tid >> 7;           // 0..3
    const int g_  = m >> 5;
    const int col = m & 31;
    const int kbase = kq * 96;
    const int grow  = g_ * HDIM + cb + col;

    // ---- weights into registers (persistent, zero per-step LDS) ----
    float wreg[96];
    {
        const float* src_ih = W_ih + (size_t)grow * IN_DIM;
        const float* src_hh = W_hh + (size_t)grow * HDIM - IN_DIM;
        #pragma unroll
        for (int i = 0; i < 96; i++) {
            int k = kbase + i;
            wreg[i] = (k < IN_DIM) ? __ldg(src_ih + k) : __ldg(src_hh + k);
        }
    }

    // ---- smem preload ----
    for (int i = tid; i < 16 * HDIM; i += NTHR) {
        int o = i >> 8, k = i & 255;
        sWo[o * WOPAD + k] = W_out[(rank * 16 + o) * HDIM + k];
    }
    if (tid < 128) sBias[tid] = b_ih[grow] + b_hh[grow];   // tid<128 -> m==tid
    if (tid < 16) sBOut[tid] = b_out[rank * 16 + tid];

    // zero act buf0 h-region + x_0 transposed into buf0
    for (int i = tid; i < KTOT * 4; i += NTHR) sAct[i] = 0.0f;
    __syncthreads();
    if (tid < 128) {
        int r = tid >> 5, k5 = tid & 31;
        float4 v = *(const float4*)(input + ((size_t)rbase + r) * IN_DIM + k5 * 4);
        sAct[(k5 * 4 + 0) * 4 + r] = v.x;
        sAct[(k5 * 4 + 1) * 4 + r] = v.y;
        sAct[(k5 * 4 + 2) * 4 + r] = v.z;
        sAct[(k5 * 4 + 3) * 4 + r] = v.w;
        // zero our slice of g_hT[grp][0] (h_0 = 0)
        g_hT[grp][0][(cb + (tid & 31)) * 4 + (tid >> 5)] = 0.0f;
    }
    __syncthreads();

    // ---- init group barrier ----
    if (tid == 0) st_rel(&g_flags[bid].v, base + 1);
    if (tid < 8) {
        const unsigned* p = &g_flags[grp * 8 + tid].v;
        while (ld_acq(p) < base + 1) { }
    }
    __syncthreads();

    const size_t Y_TOTAL = (size_t)T_STEPS * BATCH * OUT_DIM;
    const bool write_tail = (out_size >= (int)(Y_TOTAL + 2 * BATCH * HDIM));

    float c_reg = 0.0f;   // cell state for (r=tid>>5, col), threads 0-127

    for (int t = 0; t < T_STEPS; t++) {
        const int buf = t & 1;
        float* A = sAct + buf * (KTOT * 4);

        // ---- fill h region from g_hT[grp][buf] (linear, L1-bypass) ----
        if (tid < 256) {
            float4 v = __ldcg(((const float4*)g_hT[grp][buf]) + tid);
            ((float4*)A)[128 + tid] = v;
        }
        __syncthreads();

        const unsigned tgt = base + 2 + (unsigned)t;

        // ---- gate GEMM: all 16 warps, f32x2 packed, W in regs ----
        {
            const ulonglong2* av = (const ulonglong2*)(A + kbase * 4);
            unsigned long long acc01 = 0ULL, acc23 = 0ULL;
            #pragma unroll
            for (int i = 0; i < 96; i++) {
                ulonglong2 p = av[i];
                unsigned wu = __float_as_uint(wreg[i]);
                unsigned long long wp;
                asm("mov.b64 %0, {%1, %1};" : "=l"(wp) : "r"(wu));
                asm("fma.rn.f32x2 %0, %1, %2, %0;" : "+l"(acc01) : "l"(wp), "l"(p.x));
                asm("fma.rn.f32x2 %0, %1, %2, %0;" : "+l"(acc23) : "l"(wp), "l"(p.y));
            }
            unsigned u0, u1, u2, u3;
            asm("mov.b64 {%0, %1}, %2;" : "=r"(u0), "=r"(u1) : "l"(acc01));
            asm("mov.b64 {%0, %1}, %2;" : "=r"(u2), "=r"(u3) : "l"(acc23));
            *(float4*)(sP + (kq * 128 + m) * 4) =
                make_float4(__uint_as_float(u0), __uint_as_float(u1),
                            __uint_as_float(u2), __uint_as_float(u3));
        }
        __syncthreads();

        if (tid < 128) {
            // ---- reduce split-K + bias (thread = gate-col m) ----
            const float4* p4 = (const float4*)sP;
            float4 s0 = p4[tid], s1 = p4[128 + tid], s2 = p4[256 + tid], s3 = p4[384 + tid];
            float b = sBias[tid];
            *(float4*)(sG + tid * 4) = make_float4(
                s0.x + s1.x + s2.x + s3.x + b,
                s0.y + s1.y + s2.y + s3.y + b,
                s0.z + s1.z + s2.z + s3.z + b,
                s0.w + s1.w + s2.w + s3.w + b);
            asm volatile("bar.sync 1, 128;" ::: "memory");

            // ---- cell: thread (r = tid>>5, c = tid&31) ----
            const int r = tid >> 5, c = tid & 31;
            float gi = sG[(0 * 32 + c) * 4 + r];
            float gf = sG[(1 * 32 + c) * 4 + r];
            float gg = sG[(2 * 32 + c) * 4 + r];
            float go = sG[(3 * 32 + c) * 4 + r];
            float i_ = 1.0f / (1.0f + __expf(-gi));
            float f_ = 1.0f / (1.0f + __expf(-gf));
            float gv = tanhf(gg);
            float o_ = 1.0f / (1.0f + __expf(-go));
            float cn = f_ * c_reg + i_ * gv;
            float hn = o_ * tanhf(cn);
            c_reg = cn;

            __stcg(&g_hT[grp][1 - buf][(cb + c) * 4 + r], hn);

            if (t == T_STEPS - 1 && write_tail) {
                out[Y_TOTAL + (size_t)(rbase + r) * HDIM + cb + c] = hn;
                out[Y_TOTAL + BATCH * HDIM + (size_t)(rbase + r) * HDIM + cb + c] = cn;
            }
            asm volatile("bar.sync 1, 128;" ::: "memory");
            if (tid == 0) st_rel(&g_flags[bid].v, tgt);
        } else if (tid < 256) {
            // ---- warps 4-7: x_{t+1} prefetch (transposed) into other buf ----
            if (t + 1 < T_STEPS) {
                int xr = (tid - 128) >> 5, xk5 = (tid - 128) & 31;
                float4 v = __ldcg((const float4*)(input
                            + ((size_t)(t + 1) * BATCH + rbase + xr) * IN_DIM + xk5 * 4));
                float* dst = sAct + (1 - buf) * (KTOT * 4);
                dst[(xk5 * 4 + 0) * 4 + xr] = v.x;
                dst[(xk5 * 4 + 1) * 4 + xr] = v.y;
                dst[(xk5 * 4 + 2) * 4 + xr] = v.z;
                dst[(xk5 * 4 + 3) * 4 + xr] = v.w;
            }
        } else if (t > 0) {
            // ---- warps 8-15: y_{t-1} = h_t @ W_out^T ----
            const int slot = tid - 256;
            const int o = slot >> 4, ks = slot & 15;   // 16 k-splits, interleaved
            float y0 = 0.f, y1 = 0.f, y2 = 0.f, y3 = 0.f;
            const float* wo = sWo + o * WOPAD + ks;
            const float4* ah = (const float4*)(A + (IN_DIM + ks) * 4);
            #pragma unroll
            for (int i = 0; i < 16; i++) {
                float w = wo[i * 16];
                float4 hv = ah[i * 16];
                y0 += w * hv.x; y1 += w * hv.y; y2 += w * hv.z; y3 += w * hv.w;
            }
            #pragma unroll
            for (int s = 1; s <= 8; s <<= 1) {
                y0 += __shfl_xor_sync(0xffffffffu, y0, s);
                y1 += __shfl_xor_sync(0xffffffffu, y1, s);
                y2 += __shfl_xor_sync(0xffffffffu, y2, s);
                y3 += __shfl_xor_sync(0xffffffffu, y3, s);
            }
            if (ks == 0) {
                float b = sBOut[o];
                size_t yb = ((size_t)(t - 1) * BATCH + rbase) * OUT_DIM
                            + (size_t)rank * 16 + o;
                out[yb + 0 * OUT_DIM] = y0 + b;
                out[yb + 1 * OUT_DIM] = y1 + b;
                out[yb + 2 * OUT_DIM] = y2 + b;
                out[yb + 3 * OUT_DIM] = y3 + b;
            }
        }

        // ---- group poll: 8 flags, threads 0-7 ----
        if (tid < 8) {
            const unsigned* p = &g_flags[grp * 8 + tid].v;
            while (ld_acq(p) < tgt) { }
        }
        __syncthreads();
    }

    // ---- tail: y_{T-1} from h_T ----
    {
        float* A = sAct + (T_STEPS & 1) * (KTOT * 4);
        if (tid < 256) {
            float4 v = __ldcg(((const float4*)g_hT[grp][T_STEPS & 1]) + tid);
            ((float4*)A)[128 + tid] = v;
        }
        __syncthreads();
        if (tid >= 256) {
            const int slot = tid - 256;
            const int o = slot >> 4, ks = slot & 15;
            float y0 = 0.f, y1 = 0.f, y2 = 0.f, y3 = 0.f;
            const float* wo = sWo + o * WOPAD + ks;
            const float4* ah = (const float4*)(A + (IN_DIM + ks) * 4);
            #pragma unroll
            for (int i = 0; i < 16; i++) {
                float w = wo[i * 16];
                float4 hv = ah[i * 16];
                y0 += w * hv.x; y1 += w * hv.y; y2 += w * hv.z; y3 += w * hv.w;
            }
            #pragma unroll
            for (int s = 1; s <= 8; s <<= 1) {
                y0 += __shfl_xor_sync(0xffffffffu, y0, s);
                y1 += __shfl_xor_sync(0xffffffffu, y1, s);
                y2 += __shfl_xor_sync(0xffffffffu, y2, s);
                y3 += __shfl_xor_sync(0xffffffffu, y3, s);
            }
            if (ks == 0) {
                float b = sBOut[o];
                size_t yb = ((size_t)(T_STEPS - 1) * BATCH + rbase) * OUT_DIM
                            + (size_t)rank * 16 + o;
                out[yb + 0 * OUT_DIM] = y0 + b;
                out[yb + 1 * OUT_DIM] = y1 + b;
                out[yb + 2 * OUT_DIM] = y2 + b;
                out[yb + 3 * OUT_DIM] = y3 + b;
            }
        }
    }
}

extern "C" void kernel_launch(void* const* d_in, const int* in_sizes, int n_in,
                              void* d_out, int out_size) {
    const float* input = (const float*)d_in[0];
    const float* W_ih  = (const float*)d_in[1];
    const float* W_hh  = (const float*)d_in[2];
    const float* b_ih  = (const float*)d_in[3];
    const float* b_hh  = (const float*)d_in[4];
    const float* W_out = (const float*)d_in[5];
    const float* b_out = (const float*)d_in[6];
    float* out = (float*)d_out;
    (void)in_sizes; (void)n_in;

    cudaFuncSetAttribute(lstm_fat_kernel,
                         cudaFuncAttributeMaxDynamicSharedMemorySize, SMEM_BYTES);
    lstm_fat_kernel<<<NBLK, NTHR, SMEM_BYTES>>>(
        input, W_ih, W_hh, b_ih, b_hh, W_out, b_out, out, out_size);
}